// round 2
// baseline (speedup 1.0000x reference)
#include <cuda_runtime.h>
#include <cuda_bf16.h>
#include <math.h>

#define BN 4096          // number of samples
#define DK 1024          // feature dim
#define TBM 128          // GEMM tile M
#define TBK 16           // GEMM tile K
#define SPAD 132         // padded smem row stride (multiple of 4 for float4 alignment)
#define INFV 3.4e38f

// 64 MB Gram scratch (device global — no allocations allowed)
__device__ float g_G[(size_t)BN * BN];

// ---------------------------------------------------------------------------
// Gram GEMM: G[i][j] = <x_i, x_j> for lower triangle (incl. diagonal blocks).
// Triangular block grid: 32*(32+1)/2 = 528 blocks of 256 threads, 8x8/thread.
// ---------------------------------------------------------------------------
__global__ __launch_bounds__(256, 2) void gram_kernel(const float* __restrict__ X) {
    __shared__ float As[TBK][SPAD];
    __shared__ float Bs[TBK][SPAD];

    // map linear block id -> (bi, bj) with bi >= bj
    int t = blockIdx.x;
    int bi = (int)((sqrtf(8.0f * (float)t + 1.0f) - 1.0f) * 0.5f);
    while ((bi + 1) * (bi + 2) / 2 <= t) ++bi;
    while (bi * (bi + 1) / 2 > t) --bi;
    int bj = t - bi * (bi + 1) / 2;

    const int i0 = bi * TBM;
    const int j0 = bj * TBM;
    const int tid = threadIdx.x;
    const int tx = tid & 15;          // 16 x 16 thread grid
    const int ty = tid >> 4;

    float acc[8][8];
#pragma unroll
    for (int m = 0; m < 8; ++m)
#pragma unroll
        for (int n = 0; n < 8; ++n) acc[m][n] = 0.0f;

    for (int k0 = 0; k0 < DK; k0 += TBK) {
        // load 128x16 tiles of A (rows i0..) and B (rows j0..), transposed into smem
#pragma unroll
        for (int s = tid; s < 512; s += 256) {
            int row = s >> 2;
            int c4  = s & 3;
            float4 va = *(const float4*)(X + (size_t)(i0 + row) * DK + k0 + 4 * c4);
            As[4 * c4 + 0][row] = va.x;
            As[4 * c4 + 1][row] = va.y;
            As[4 * c4 + 2][row] = va.z;
            As[4 * c4 + 3][row] = va.w;
            float4 vb = *(const float4*)(X + (size_t)(j0 + row) * DK + k0 + 4 * c4);
            Bs[4 * c4 + 0][row] = vb.x;
            Bs[4 * c4 + 1][row] = vb.y;
            Bs[4 * c4 + 2][row] = vb.z;
            Bs[4 * c4 + 3][row] = vb.w;
        }
        __syncthreads();

#pragma unroll
        for (int kk = 0; kk < TBK; ++kk) {
            float ra[8], rb[8];
            float4 a0 = *(const float4*)&As[kk][ty * 8];
            float4 a1 = *(const float4*)&As[kk][ty * 8 + 4];
            float4 b0 = *(const float4*)&Bs[kk][tx * 8];
            float4 b1 = *(const float4*)&Bs[kk][tx * 8 + 4];
            ra[0] = a0.x; ra[1] = a0.y; ra[2] = a0.z; ra[3] = a0.w;
            ra[4] = a1.x; ra[5] = a1.y; ra[6] = a1.z; ra[7] = a1.w;
            rb[0] = b0.x; rb[1] = b0.y; rb[2] = b0.z; rb[3] = b0.w;
            rb[4] = b1.x; rb[5] = b1.y; rb[6] = b1.z; rb[7] = b1.w;
#pragma unroll
            for (int m = 0; m < 8; ++m)
#pragma unroll
                for (int n = 0; n < 8; ++n)
                    acc[m][n] = fmaf(ra[m], rb[n], acc[m][n]);
        }
        __syncthreads();
    }

    // store 8x8 per thread as float4
#pragma unroll
    for (int m = 0; m < 8; ++m) {
        int row = i0 + ty * 8 + m;
        float* dst = g_G + (size_t)row * BN + j0 + tx * 8;
        float4 v0 = make_float4(acc[m][0], acc[m][1], acc[m][2], acc[m][3]);
        float4 v1 = make_float4(acc[m][4], acc[m][5], acc[m][6], acc[m][7]);
        *(float4*)(dst)     = v0;
        *(float4*)(dst + 4) = v1;
    }
}

// ---------------------------------------------------------------------------
// Sequential awareness scan: one CTA of 1024 threads.
// State: ref index list (u16 in smem), norms = diag(G) (smem), labels (u8 smem),
// scalars (min_d, max_d, R, n_refs) owned by thread 0 via smem.
// ---------------------------------------------------------------------------
__global__ __launch_bounds__(1024, 1) void scan_kernel(const int* __restrict__ labels,
                                                       float* __restrict__ out) {
    __shared__ float s_norm[BN];
    __shared__ unsigned short s_ridx[BN];
    __shared__ unsigned char s_lab[BN];
    __shared__ float r_min[32];
    __shared__ int   r_arg[32];
    __shared__ float r_max[32];
    __shared__ float sh_minD, sh_maxD, sh_R;
    __shared__ int   sh_n;

    const int tid = threadIdx.x;

    for (int i = tid; i < BN; i += 1024) {
        s_norm[i] = g_G[(size_t)i * BN + i];
        s_lab[i]  = (unsigned char)labels[i];
    }
    if (tid == 0) { sh_minD = INFV; sh_maxD = 0.0f; sh_R = 1.0f; sh_n = 0; }
    __syncthreads();

    for (int i = 0; i < BN; ++i) {
        const int n = sh_n;
        const float ni = s_norm[i];
        const float* __restrict__ Grow = g_G + (size_t)i * BN;

        float lmin = INFV;
        int   larg = 0x7fffffff;   // empty threads lose ties at INF
        float lmax = -INFV;
        for (int j = tid; j < n; j += 1024) {
            int r = s_ridx[j];
            float d2 = fmaf(-2.0f, __ldg(Grow + r), ni + s_norm[r]);
            if (d2 < lmin) { lmin = d2; larg = j; }   // strict < keeps lowest j per thread
            lmax = fmaxf(lmax, d2);
        }

        // warp reduce (min+argmin with lowest-index tiebreak, max)
#pragma unroll
        for (int off = 16; off > 0; off >>= 1) {
            float v = __shfl_down_sync(0xffffffffu, lmin, off);
            int   a = __shfl_down_sync(0xffffffffu, larg, off);
            float m = __shfl_down_sync(0xffffffffu, lmax, off);
            if (v < lmin || (v == lmin && a < larg)) { lmin = v; larg = a; }
            lmax = fmaxf(lmax, m);
        }
        const int wid = tid >> 5, lane = tid & 31;
        if (lane == 0) { r_min[wid] = lmin; r_arg[wid] = larg; r_max[wid] = lmax; }
        __syncthreads();

        if (tid == 0) {
            float bm = r_min[0]; int ba = r_arg[0]; float bx = r_max[0];
#pragma unroll
            for (int w = 1; w < 32; ++w) {
                float v = r_min[w]; int a = r_arg[w];
                if (v < bm || (v == bm && a < ba)) { bm = v; ba = a; }
                bx = fmaxf(bx, r_max[w]);
            }
            const bool is_first = (i == 0);
            const float min_act = sqrtf(fmaxf(bm, 0.0f));   // monotone: min(sqrt) = sqrt(min)
            const bool insert = is_first || (min_act > sh_R);

            float pred;
            if (insert) {
                s_ridx[n] = (unsigned short)i;
                sh_n = n + 1;
                pred = (float)s_lab[i];          // self-distance 0 wins the argmin
            } else {
                pred = (float)s_lab[s_ridx[ba]];
            }
            if (!is_first) {
                const float max_act = sqrtf(fmaxf(bx, 0.0f));
                sh_minD = fminf(sh_minD, min_act);
                sh_maxD = fmaxf(sh_maxD, max_act);
                sh_R = (sh_minD + sh_maxD) / 3.0f;
            }
            out[i] = pred;
        }
        __syncthreads();
    }
}

// ---------------------------------------------------------------------------
extern "C" void kernel_launch(void* const* d_in, const int* in_sizes, int n_in,
                              void* d_out, int out_size) {
    const float* x      = (const float*)d_in[0];   // [4096, 1, 1024] fp32
    const int*   labels = (const int*)d_in[1];     // [4096] int32
    float*       out    = (float*)d_out;           // [4096] fp32

    const int nb = BN / TBM;                       // 32
    const int nblocks = nb * (nb + 1) / 2;         // 528 triangular blocks
    gram_kernel<<<nblocks, 256>>>(x);
    scan_kernel<<<1, 1024>>>(labels, out);
}

// round 6
// speedup vs baseline: 10.2210x; 10.2210x over previous
#include <cuda_runtime.h>
#include <cuda_bf16.h>
#include <math.h>

#define BN 4096          // number of samples
#define DK 1024          // feature dim
#define TBM 128          // GEMM tile M
#define TBK 16           // GEMM tile K
#define SPAD 132         // padded smem row stride
#define INFV 3.4e38f

// Device scratch (no allocations allowed)
__device__ float g_G[(size_t)BN * BN];                  // Gram lower triangle (fallback path)
__device__ float g_norm[BN];                            // ||x_i||^2
__device__ unsigned long long g_rowmin[BN];             // packed (d2_bits<<32 | j), min over j<i
__device__ unsigned int g_rowmax[BN];                   // d2_bits, max over j<i

// ---------------------------------------------------------------------------
__global__ void init_stats() {
    int i = blockIdx.x * blockDim.x + threadIdx.x;
    if (i < BN) { g_rowmin[i] = ~0ull; g_rowmax[i] = 0u; }
}

// One warp per row: ||x_row||^2
__global__ __launch_bounds__(256) void norm_kernel(const float* __restrict__ X) {
    int w = (blockIdx.x * blockDim.x + threadIdx.x) >> 5;   // row
    int lane = threadIdx.x & 31;
    const float4* row = (const float4*)(X + (size_t)w * DK);
    float s = 0.0f;
#pragma unroll
    for (int c = lane; c < DK / 4; c += 32) {
        float4 v = row[c];
        s = fmaf(v.x, v.x, s); s = fmaf(v.y, v.y, s);
        s = fmaf(v.z, v.z, s); s = fmaf(v.w, v.w, s);
    }
#pragma unroll
    for (int off = 16; off > 0; off >>= 1) s += __shfl_xor_sync(0xffffffffu, s, off);
    if (lane == 0) g_norm[w] = s;
}

// ---------------------------------------------------------------------------
// Gram GEMM (lower triangle) + fused per-row min/argmin/max of d^2 over j<i.
// ---------------------------------------------------------------------------
__global__ __launch_bounds__(256, 2) void gram_kernel(const float* __restrict__ X) {
    __shared__ float As[TBK][SPAD];
    __shared__ float Bs[TBK][SPAD];

    int t = blockIdx.x;
    int bi = (int)((sqrtf(8.0f * (float)t + 1.0f) - 1.0f) * 0.5f);
    while ((bi + 1) * (bi + 2) / 2 <= t) ++bi;
    while (bi * (bi + 1) / 2 > t) --bi;
    int bj = t - bi * (bi + 1) / 2;

    const int i0 = bi * TBM;
    const int j0 = bj * TBM;
    const int tid = threadIdx.x;
    const int tx = tid & 15;
    const int ty = tid >> 4;

    float acc[8][8];
#pragma unroll
    for (int m = 0; m < 8; ++m)
#pragma unroll
        for (int n = 0; n < 8; ++n) acc[m][n] = 0.0f;

    for (int k0 = 0; k0 < DK; k0 += TBK) {
#pragma unroll
        for (int s = tid; s < 512; s += 256) {
            int row = s >> 2;
            int c4  = s & 3;
            float4 va = *(const float4*)(X + (size_t)(i0 + row) * DK + k0 + 4 * c4);
            As[4 * c4 + 0][row] = va.x; As[4 * c4 + 1][row] = va.y;
            As[4 * c4 + 2][row] = va.z; As[4 * c4 + 3][row] = va.w;
            float4 vb = *(const float4*)(X + (size_t)(j0 + row) * DK + k0 + 4 * c4);
            Bs[4 * c4 + 0][row] = vb.x; Bs[4 * c4 + 1][row] = vb.y;
            Bs[4 * c4 + 2][row] = vb.z; Bs[4 * c4 + 3][row] = vb.w;
        }
        __syncthreads();

#pragma unroll
        for (int kk = 0; kk < TBK; ++kk) {
            float ra[8], rb[8];
            float4 a0 = *(const float4*)&As[kk][ty * 8];
            float4 a1 = *(const float4*)&As[kk][ty * 8 + 4];
            float4 b0 = *(const float4*)&Bs[kk][tx * 8];
            float4 b1 = *(const float4*)&Bs[kk][tx * 8 + 4];
            ra[0]=a0.x; ra[1]=a0.y; ra[2]=a0.z; ra[3]=a0.w;
            ra[4]=a1.x; ra[5]=a1.y; ra[6]=a1.z; ra[7]=a1.w;
            rb[0]=b0.x; rb[1]=b0.y; rb[2]=b0.z; rb[3]=b0.w;
            rb[4]=b1.x; rb[5]=b1.y; rb[6]=b1.z; rb[7]=b1.w;
#pragma unroll
            for (int m = 0; m < 8; ++m)
#pragma unroll
                for (int n = 0; n < 8; ++n)
                    acc[m][n] = fmaf(ra[m], rb[n], acc[m][n]);
        }
        __syncthreads();
    }

    // Store G tile (fallback path consumes it)
#pragma unroll
    for (int m = 0; m < 8; ++m) {
        int row = i0 + ty * 8 + m;
        float* dst = g_G + (size_t)row * BN + j0 + tx * 8;
        *(float4*)(dst)     = make_float4(acc[m][0], acc[m][1], acc[m][2], acc[m][3]);
        *(float4*)(dst + 4) = make_float4(acc[m][4], acc[m][5], acc[m][6], acc[m][7]);
    }

    // Fused epilogue: d^2(i,j) = ni + nj - 2*G, reduce min/argmin/max per row over j<i
    const bool diag = (bi == bj);
    float nj[8];
#pragma unroll
    for (int n = 0; n < 8; ++n) nj[n] = __ldg(g_norm + j0 + tx * 8 + n);

#pragma unroll
    for (int m = 0; m < 8; ++m) {
        const int gi = i0 + ty * 8 + m;
        const float ni = __ldg(g_norm + gi);
        unsigned long long kmin = ~0ull;
        float vmax = 0.0f;
#pragma unroll
        for (int n = 0; n < 8; ++n) {
            const int gj = j0 + tx * 8 + n;
            if (!diag || gj < gi) {
                float d2 = fmaf(-2.0f, acc[m][n], ni + nj[n]);
                d2 = fmaxf(d2, 0.0f);
                unsigned long long key =
                    ((unsigned long long)__float_as_uint(d2) << 32) | (unsigned)gj;
                kmin = (key < kmin) ? key : kmin;
                vmax = fmaxf(vmax, d2);
            }
        }
        // reduce across the 16-lane tx group
#pragma unroll
        for (int off = 8; off >= 1; off >>= 1) {
            unsigned long long ok = __shfl_xor_sync(0xffffffffu, kmin, off);
            float om = __shfl_xor_sync(0xffffffffu, vmax, off);
            kmin = (ok < kmin) ? ok : kmin;
            vmax = fmaxf(vmax, om);
        }
        if (tx == 0 && kmin != ~0ull) {
            atomicMin(g_rowmin + gi, kmin);
            atomicMax(g_rowmax + gi, __float_as_uint(vmax));
        }
    }
}

// ---------------------------------------------------------------------------
// Speculative scan: if every step inserts (refs == all previous), the per-step
// reductions are exactly the precomputed row stats; prefix min/max + violation
// check run fully parallel. Exact fallback loop from the first violation.
// ---------------------------------------------------------------------------
__global__ __launch_bounds__(1024, 1) void scan_kernel(const int* __restrict__ labels,
                                                       float* __restrict__ out) {
    extern __shared__ char dyn[];
    float* s_minA = (float*)dyn;                              // 16KB  min_act per row
    float* s_maxA = (float*)(dyn + 16384);                    // 16KB  max_act per row
    float* s_norm = (float*)(dyn + 32768);                    // 16KB  (fallback)
    unsigned short* s_ridx = (unsigned short*)(dyn + 49152);  // 8KB   (fallback)
    unsigned char*  s_lab  = (unsigned char*)(dyn + 57344);   // 4KB   (fallback)

    __shared__ float wmin[32], wmax[32];
    __shared__ int s_k;
    __shared__ float r_min[32]; __shared__ int r_arg[32]; __shared__ float r_max[32];
    __shared__ float sh_minD, sh_maxD, sh_R; __shared__ int sh_n;

    const int tid = threadIdx.x;
    const int lane = tid & 31, wid = tid >> 5;

    for (int i = tid; i < BN; i += 1024) {
        if (i == 0) { s_minA[0] = INFV; s_maxA[0] = 0.0f; }
        else {
            unsigned long long p = g_rowmin[i];
            s_minA[i] = sqrtf(__uint_as_float((unsigned)(p >> 32)));
            s_maxA[i] = sqrtf(__uint_as_float(g_rowmax[i]));
        }
    }
    if (tid == 0) s_k = BN;
    __syncthreads();

    // ---- block-wide prefix min/max, 4 contiguous elems per thread ----
    const int base = tid * 4;
    float e0 = s_minA[base], e1 = s_minA[base+1], e2 = s_minA[base+2], e3 = s_minA[base+3];
    float f0 = s_maxA[base], f1 = s_maxA[base+1], f2 = s_maxA[base+2], f3 = s_maxA[base+3];
    float im = fminf(fminf(e0, e1), fminf(e2, e3));   // thread aggregate (min)
    float ix = fmaxf(fmaxf(f0, f1), fmaxf(f2, f3));   // thread aggregate (max)

#pragma unroll
    for (int off = 1; off < 32; off <<= 1) {
        float o  = __shfl_up_sync(0xffffffffu, im, off); if (lane >= off) im = fminf(im, o);
        float o2 = __shfl_up_sync(0xffffffffu, ix, off); if (lane >= off) ix = fmaxf(ix, o2);
    }
    if (lane == 31) { wmin[wid] = im; wmax[wid] = ix; }
    __syncthreads();
    if (wid == 0) {
        float a = wmin[lane], b = wmax[lane];
#pragma unroll
        for (int off = 1; off < 32; off <<= 1) {
            float o  = __shfl_up_sync(0xffffffffu, a, off); if (lane >= off) a = fminf(a, o);
            float o2 = __shfl_up_sync(0xffffffffu, b, off); if (lane >= off) b = fmaxf(b, o2);
        }
        wmin[lane] = a; wmax[lane] = b;   // inclusive totals per warp
    }
    __syncthreads();

    float excl_min = INFV, excl_max = 0.0f;
    if (wid > 0) { excl_min = wmin[wid - 1]; excl_max = wmax[wid - 1]; }
    float pm = __shfl_up_sync(0xffffffffu, im, 1);
    float px = __shfl_up_sync(0xffffffffu, ix, 1);
    if (lane > 0) { excl_min = fminf(excl_min, pm); excl_max = fmaxf(excl_max, px); }

    // ---- violation check: insert_i requires min_act_i > R entering step i ----
    {
        float run_min = excl_min, run_max = excl_max;
        float e[4] = {e0, e1, e2, e3};
        float f[4] = {f0, f1, f2, f3};
        int myviol = BN;
#pragma unroll
        for (int tI = 0; tI < 4; ++tI) {
            int i = base + tI;
            if (i >= 1) {
                float Rin = (i <= 1) ? 1.0f : (run_min + run_max) / 3.0f;
                if (!(e[tI] > Rin) && myviol == BN) myviol = i;
            }
            run_min = fminf(run_min, e[tI]);
            run_max = fmaxf(run_max, f[tI]);
        }
        if (myviol < BN) atomicMin(&s_k, myviol);
    }
    __syncthreads();
    const int k = s_k;

    // Fast-path outputs: every inserted step predicts its own label
    for (int i = tid; i < k; i += 1024) out[i] = (float)labels[i];
    if (k == BN) return;

    // ================= exact fallback from the first non-insert =================
    if (tid == 0) {
        unsigned arg = (unsigned)(g_rowmin[k] & 0xffffffffu);  // argmin over refs {0..k-1}
        out[k] = (float)labels[arg];
        float a = INFV, b = 0.0f;
        for (int i = 1; i <= k; ++i) { a = fminf(a, s_minA[i]); b = fmaxf(b, s_maxA[i]); }
        sh_minD = a; sh_maxD = b; sh_R = (a + b) / 3.0f; sh_n = k;
    }
    for (int i = tid; i < BN; i += 1024) {
        s_norm[i] = g_norm[i];
        s_lab[i]  = (unsigned char)labels[i];
    }
    for (int j = tid; j < k; j += 1024) s_ridx[j] = (unsigned short)j;
    __syncthreads();

    for (int i = k + 1; i < BN; ++i) {
        const int n = sh_n;
        const float ni = s_norm[i];
        const float* __restrict__ Grow = g_G + (size_t)i * BN;

        float lmin = INFV;
        int   larg = 0x7fffffff;
        float lmax = -INFV;
        for (int j = tid; j < n; j += 1024) {
            int r = s_ridx[j];
            float d2 = fmaf(-2.0f, __ldg(Grow + r), ni + s_norm[r]);
            if (d2 < lmin) { lmin = d2; larg = j; }
            lmax = fmaxf(lmax, d2);
        }
#pragma unroll
        for (int off = 16; off > 0; off >>= 1) {
            float v = __shfl_down_sync(0xffffffffu, lmin, off);
            int   a = __shfl_down_sync(0xffffffffu, larg, off);
            float m = __shfl_down_sync(0xffffffffu, lmax, off);
            if (v < lmin || (v == lmin && a < larg)) { lmin = v; larg = a; }
            lmax = fmaxf(lmax, m);
        }
        if (lane == 0) { r_min[wid] = lmin; r_arg[wid] = larg; r_max[wid] = lmax; }
        __syncthreads();

        if (tid == 0) {
            float bm = r_min[0]; int ba = r_arg[0]; float bx = r_max[0];
#pragma unroll
            for (int w = 1; w < 32; ++w) {
                float v = r_min[w]; int a = r_arg[w];
                if (v < bm || (v == bm && a < ba)) { bm = v; ba = a; }
                bx = fmaxf(bx, r_max[w]);
            }
            const float min_act = sqrtf(fmaxf(bm, 0.0f));
            const bool insert = (min_act > sh_R);
            float pred;
            if (insert) {
                s_ridx[n] = (unsigned short)i;
                sh_n = n + 1;
                pred = (float)s_lab[i];
            } else {
                pred = (float)s_lab[s_ridx[ba]];
            }
            const float max_act = sqrtf(fmaxf(bx, 0.0f));
            sh_minD = fminf(sh_minD, min_act);
            sh_maxD = fmaxf(sh_maxD, max_act);
            sh_R = (sh_minD + sh_maxD) / 3.0f;
            out[i] = pred;
        }
        __syncthreads();
    }
}

// ---------------------------------------------------------------------------
extern "C" void kernel_launch(void* const* d_in, const int* in_sizes, int n_in,
                              void* d_out, int out_size) {
    const float* x      = (const float*)d_in[0];
    const int*   labels = (const int*)d_in[1];
    float*       out    = (float*)d_out;

    static bool attr_set = false;
    if (!attr_set) {
        cudaFuncSetAttribute(scan_kernel, cudaFuncAttributeMaxDynamicSharedMemorySize, 61440);
        attr_set = true;
    }

    init_stats<<<BN / 256, 256>>>();
    norm_kernel<<<BN / 8, 256>>>(x);                 // 8 rows (warps) per block
    const int nb = BN / TBM;
    gram_kernel<<<nb * (nb + 1) / 2, 256>>>(x);
    scan_kernel<<<1, 1024, 61440>>>(labels, out);
}

// round 8
// speedup vs baseline: 75.1932x; 7.3568x over previous
#include <cuda_runtime.h>
#include <cuda_bf16.h>
#include <math.h>
#include <stdint.h>

#define BN 4096          // samples
#define DK 1024          // feature dim
#define TM 128           // tile M = N
#define KC 32            // K elems per chunk
#define NCHUNK (DK / KC) // 32
#define ROWB 80          // padded smem row stride in bytes (40 bf16)
#define ATILE (TM * ROWB)            // 10240 B per operand tile
#define BUFB  (2 * ATILE)            // one buffer = A + B
#define INFV 3.4e38f

// ---------------- device scratch (no allocations allowed) ------------------
__device__ float g_G[(size_t)BN * BN];                  // Gram (fallback path)
__device__ __nv_bfloat16 g_Xb[(size_t)BN * DK];         // bf16 copy of X
__device__ float g_norm[BN];                            // ||x_i||^2 (fp32)
__device__ unsigned long long g_rowmin[BN];             // packed (d2_bits<<32 | j)
__device__ unsigned int g_rowmax[BN];                   // d2_bits max over j<i

__device__ __forceinline__ uint32_t smem_to_u32(const void* p) {
    uint32_t a;
    asm("{ .reg .u64 t; cvta.to.shared.u64 t, %1; cvt.u32.u64 %0, t; }" : "=r"(a) : "l"(p));
    return a;
}

// ---------------------------------------------------------------------------
__global__ void init_stats() {
    int i = blockIdx.x * blockDim.x + threadIdx.x;
    if (i < BN) { g_rowmin[i] = ~0ull; g_rowmax[i] = 0u; }
}

__global__ void convert_kernel(const float* __restrict__ X) {
    int t = blockIdx.x * blockDim.x + threadIdx.x;
    float4 v = ((const float4*)X)[t];
    __nv_bfloat162 lo = __floats2bfloat162_rn(v.x, v.y);
    __nv_bfloat162 hi = __floats2bfloat162_rn(v.z, v.w);
    uint2 o;
    o.x = *(unsigned*)&lo; o.y = *(unsigned*)&hi;
    ((uint2*)g_Xb)[t] = o;
}

__global__ __launch_bounds__(256) void norm_kernel(const float* __restrict__ X) {
    int w = (blockIdx.x * blockDim.x + threadIdx.x) >> 5;
    int lane = threadIdx.x & 31;
    const float4* row = (const float4*)(X + (size_t)w * DK);
    float s = 0.0f;
#pragma unroll
    for (int c = lane; c < DK / 4; c += 32) {
        float4 v = row[c];
        s = fmaf(v.x, v.x, s); s = fmaf(v.y, v.y, s);
        s = fmaf(v.z, v.z, s); s = fmaf(v.w, v.w, s);
    }
#pragma unroll
    for (int off = 16; off > 0; off >>= 1) s += __shfl_xor_sync(0xffffffffu, s, off);
    if (lane == 0) g_norm[w] = s;
}

// ---------------------------------------------------------------------------
// bf16 mma.sync Gram GEMM (lower triangle) + fused row stats + fp32 G store.
// 8 warps: 4(m) x 2(n); warp tile 32x64; m16n8k16 fragments; cp.async double buf.
// ---------------------------------------------------------------------------
__global__ __launch_bounds__(256) void gram_mma() {
    __shared__ __align__(128) char smem[2 * BUFB];   // 40960 B

    const int tid = threadIdx.x;
    const int lane = tid & 31;
    const int wid = tid >> 5;
    const uint32_t sbase = smem_to_u32(smem);

    // triangular block map
    int t = blockIdx.x;
    int bi = (int)((sqrtf(8.0f * (float)t + 1.0f) - 1.0f) * 0.5f);
    while ((bi + 1) * (bi + 2) / 2 <= t) ++bi;
    while (bi * (bi + 1) / 2 > t) --bi;
    const int bj = t - bi * (bi + 1) / 2;
    const int i0 = bi * TM, j0 = bj * TM;

    const int warpM = wid & 3;          // 0..3
    const int warpN = wid >> 2;         // 0..1
    const int mbase = warpM * 32;
    const int nbase = warpN * 64;

    float acc[2][8][4];
#pragma unroll
    for (int a = 0; a < 2; ++a)
#pragma unroll
        for (int b = 0; b < 8; ++b)
#pragma unroll
            for (int c = 0; c < 4; ++c) acc[a][b][c] = 0.0f;

    // cp.async loader: thread -> row = tid>>1, byte off = (tid&1)*32 (+0,+16)
    const int lrow = tid >> 1;
    const int lob  = (tid & 1) * 32;
    const __nv_bfloat16* srcArow = g_Xb + (size_t)(i0 + lrow) * DK;
    const __nv_bfloat16* srcBrow = g_Xb + (size_t)(j0 + lrow) * DK;

    auto load_chunk = [&](int c, int buf) {
        uint32_t dA = sbase + buf * BUFB + lrow * ROWB + lob;
        uint32_t dB = dA + ATILE;
        const char* sA = (const char*)(srcArow + c * KC) + lob;
        const char* sB = (const char*)(srcBrow + c * KC) + lob;
        asm volatile("cp.async.ca.shared.global [%0], [%1], 16;" :: "r"(dA), "l"(sA));
        asm volatile("cp.async.ca.shared.global [%0], [%1], 16;" :: "r"(dA + 16), "l"(sA + 16));
        asm volatile("cp.async.ca.shared.global [%0], [%1], 16;" :: "r"(dB), "l"(sB));
        asm volatile("cp.async.ca.shared.global [%0], [%1], 16;" :: "r"(dB + 16), "l"(sB + 16));
        asm volatile("cp.async.commit_group;" ::: "memory");
    };

    // ldmatrix lane address components (bytes within tile)
    const uint32_t aoffs = (uint32_t)((mbase + (lane & 15)) * ROWB + ((lane >> 4) << 3) * 2);
    const int brow = ((lane >> 4) << 3) + (lane & 7);
    const uint32_t boffs = (uint32_t)((nbase + brow) * ROWB + (((lane >> 3) & 1) << 3) * 2);

    load_chunk(0, 0);

    for (int c = 0; c < NCHUNK; ++c) {
        asm volatile("cp.async.wait_group 0;" ::: "memory");
        __syncthreads();
        if (c + 1 < NCHUNK) load_chunk(c + 1, (c + 1) & 1);

        const uint32_t tA = sbase + (c & 1) * BUFB;
        const uint32_t tB = tA + ATILE;

#pragma unroll
        for (int ks = 0; ks < 2; ++ks) {
            const uint32_t kb = ks * 32;   // 16 elems * 2B
            uint32_t a0[4], a1[4];
            asm volatile("ldmatrix.sync.aligned.m8n8.x4.shared.b16 {%0,%1,%2,%3}, [%4];"
                         : "=r"(a0[0]), "=r"(a0[1]), "=r"(a0[2]), "=r"(a0[3])
                         : "r"(tA + aoffs + kb));
            asm volatile("ldmatrix.sync.aligned.m8n8.x4.shared.b16 {%0,%1,%2,%3}, [%4];"
                         : "=r"(a1[0]), "=r"(a1[1]), "=r"(a1[2]), "=r"(a1[3])
                         : "r"(tA + aoffs + 16 * ROWB + kb));
#pragma unroll
            for (int np = 0; np < 4; ++np) {
                uint32_t bfr[4];
                asm volatile("ldmatrix.sync.aligned.m8n8.x4.shared.b16 {%0,%1,%2,%3}, [%4];"
                             : "=r"(bfr[0]), "=r"(bfr[1]), "=r"(bfr[2]), "=r"(bfr[3])
                             : "r"(tB + boffs + np * 16 * ROWB + kb));
#pragma unroll
                for (int h = 0; h < 2; ++h) {
                    float* c0 = acc[0][2 * np + h];
                    float* c1 = acc[1][2 * np + h];
                    asm volatile(
                        "mma.sync.aligned.m16n8k16.row.col.f32.bf16.bf16.f32 "
                        "{%0,%1,%2,%3}, {%4,%5,%6,%7}, {%8,%9}, {%0,%1,%2,%3};"
                        : "+f"(c0[0]), "+f"(c0[1]), "+f"(c0[2]), "+f"(c0[3])
                        : "r"(a0[0]), "r"(a0[1]), "r"(a0[2]), "r"(a0[3]),
                          "r"(bfr[2 * h]), "r"(bfr[2 * h + 1]));
                    asm volatile(
                        "mma.sync.aligned.m16n8k16.row.col.f32.bf16.bf16.f32 "
                        "{%0,%1,%2,%3}, {%4,%5,%6,%7}, {%8,%9}, {%0,%1,%2,%3};"
                        : "+f"(c1[0]), "+f"(c1[1]), "+f"(c1[2]), "+f"(c1[3])
                        : "r"(a1[0]), "r"(a1[1]), "r"(a1[2]), "r"(a1[3]),
                          "r"(bfr[2 * h]), "r"(bfr[2 * h + 1]));
                }
            }
        }
    }

    // ---------------- epilogue: stats + fp32 G store from fragments ---------
#pragma unroll
    for (int mf = 0; mf < 2; ++mf) {
        const int r_lo = i0 + mbase + mf * 16 + (lane >> 2);
        const int r_hi = r_lo + 8;
        const float ni_lo = __ldg(g_norm + r_lo);
        const float ni_hi = __ldg(g_norm + r_hi);
        unsigned long long kmin_lo = ~0ull, kmin_hi = ~0ull;
        float vmax_lo = 0.0f, vmax_hi = 0.0f;
        float* growL = g_G + (size_t)r_lo * BN + j0;
        float* growH = g_G + (size_t)r_hi * BN + j0;

#pragma unroll
        for (int nf = 0; nf < 8; ++nf) {
            const int gj = j0 + nbase + nf * 8 + 2 * (lane & 3);
            const float nj0 = __ldg(g_norm + gj);
            const float nj1 = __ldg(g_norm + gj + 1);
            const float* cf0 = acc[mf][nf];

            *(float2*)(growL + nbase + nf * 8 + 2 * (lane & 3)) = make_float2(cf0[0], cf0[1]);
            *(float2*)(growH + nbase + nf * 8 + 2 * (lane & 3)) = make_float2(cf0[2], cf0[3]);

#pragma unroll
            for (int e = 0; e < 2; ++e) {
                const int gje = gj + e;
                const float nje = e ? nj1 : nj0;
                if (gje < r_lo) {
                    float d2 = fmaxf(fmaf(-2.0f, cf0[e], ni_lo + nje), 0.0f);
                    unsigned long long key =
                        ((unsigned long long)__float_as_uint(d2) << 32) | (unsigned)gje;
                    if (key < kmin_lo) kmin_lo = key;
                    vmax_lo = fmaxf(vmax_lo, d2);
                }
                if (gje < r_hi) {
                    float d2 = fmaxf(fmaf(-2.0f, cf0[2 + e], ni_hi + nje), 0.0f);
                    unsigned long long key =
                        ((unsigned long long)__float_as_uint(d2) << 32) | (unsigned)gje;
                    if (key < kmin_hi) kmin_hi = key;
                    vmax_hi = fmaxf(vmax_hi, d2);
                }
            }
        }
        // reduce across the 4-lane column group (lanes sharing a row)
#pragma unroll
        for (int off = 1; off <= 2; off <<= 1) {
            unsigned long long o;
            float m;
            o = __shfl_xor_sync(0xffffffffu, kmin_lo, off); if (o < kmin_lo) kmin_lo = o;
            m = __shfl_xor_sync(0xffffffffu, vmax_lo, off); vmax_lo = fmaxf(vmax_lo, m);
            o = __shfl_xor_sync(0xffffffffu, kmin_hi, off); if (o < kmin_hi) kmin_hi = o;
            m = __shfl_xor_sync(0xffffffffu, vmax_hi, off); vmax_hi = fmaxf(vmax_hi, m);
        }
        if ((lane & 3) == 0) {
            if (kmin_lo != ~0ull) {
                atomicMin(g_rowmin + r_lo, kmin_lo);
                atomicMax(g_rowmax + r_lo, __float_as_uint(vmax_lo));
            }
            if (kmin_hi != ~0ull) {
                atomicMin(g_rowmin + r_hi, kmin_hi);
                atomicMax(g_rowmax + r_hi, __float_as_uint(vmax_hi));
            }
        }
    }
}

// ---------------------------------------------------------------------------
// Speculative scan (unchanged): parallel prefix + violation check, exact
// fallback loop from first non-insert (reads g_G).
// ---------------------------------------------------------------------------
__global__ __launch_bounds__(1024, 1) void scan_kernel(const int* __restrict__ labels,
                                                       float* __restrict__ out) {
    extern __shared__ char dyn[];
    float* s_minA = (float*)dyn;
    float* s_maxA = (float*)(dyn + 16384);
    float* s_norm = (float*)(dyn + 32768);
    unsigned short* s_ridx = (unsigned short*)(dyn + 49152);
    unsigned char*  s_lab  = (unsigned char*)(dyn + 57344);

    __shared__ float wmin[32], wmax[32];
    __shared__ int s_k;
    __shared__ float r_min[32]; __shared__ int r_arg[32]; __shared__ float r_max[32];
    __shared__ float sh_minD, sh_maxD, sh_R; __shared__ int sh_n;

    const int tid = threadIdx.x;
    const int lane = tid & 31, wid = tid >> 5;

    for (int i = tid; i < BN; i += 1024) {
        if (i == 0) { s_minA[0] = INFV; s_maxA[0] = 0.0f; }
        else {
            unsigned long long p = g_rowmin[i];
            s_minA[i] = sqrtf(__uint_as_float((unsigned)(p >> 32)));
            s_maxA[i] = sqrtf(__uint_as_float(g_rowmax[i]));
        }
    }
    if (tid == 0) s_k = BN;
    __syncthreads();

    const int base = tid * 4;
    float e0 = s_minA[base], e1 = s_minA[base+1], e2 = s_minA[base+2], e3 = s_minA[base+3];
    float f0 = s_maxA[base], f1 = s_maxA[base+1], f2 = s_maxA[base+2], f3 = s_maxA[base+3];
    float im = fminf(fminf(e0, e1), fminf(e2, e3));
    float ix = fmaxf(fmaxf(f0, f1), fmaxf(f2, f3));

#pragma unroll
    for (int off = 1; off < 32; off <<= 1) {
        float o  = __shfl_up_sync(0xffffffffu, im, off); if (lane >= off) im = fminf(im, o);
        float o2 = __shfl_up_sync(0xffffffffu, ix, off); if (lane >= off) ix = fmaxf(ix, o2);
    }
    if (lane == 31) { wmin[wid] = im; wmax[wid] = ix; }
    __syncthreads();
    if (wid == 0) {
        float a = wmin[lane], b = wmax[lane];
#pragma unroll
        for (int off = 1; off < 32; off <<= 1) {
            float o  = __shfl_up_sync(0xffffffffu, a, off); if (lane >= off) a = fminf(a, o);
            float o2 = __shfl_up_sync(0xffffffffu, b, off); if (lane >= off) b = fmaxf(b, o2);
        }
        wmin[lane] = a; wmax[lane] = b;
    }
    __syncthreads();

    float excl_min = INFV, excl_max = 0.0f;
    if (wid > 0) { excl_min = wmin[wid - 1]; excl_max = wmax[wid - 1]; }
    float pm = __shfl_up_sync(0xffffffffu, im, 1);
    float px = __shfl_up_sync(0xffffffffu, ix, 1);
    if (lane > 0) { excl_min = fminf(excl_min, pm); excl_max = fmaxf(excl_max, px); }

    {
        float run_min = excl_min, run_max = excl_max;
        float e[4] = {e0, e1, e2, e3};
        float f[4] = {f0, f1, f2, f3};
        int myviol = BN;
#pragma unroll
        for (int tI = 0; tI < 4; ++tI) {
            int i = base + tI;
            if (i >= 1) {
                float Rin = (i <= 1) ? 1.0f : (run_min + run_max) / 3.0f;
                if (!(e[tI] > Rin) && myviol == BN) myviol = i;
            }
            run_min = fminf(run_min, e[tI]);
            run_max = fmaxf(run_max, f[tI]);
        }
        if (myviol < BN) atomicMin(&s_k, myviol);
    }
    __syncthreads();
    const int k = s_k;

    for (int i = tid; i < k; i += 1024) out[i] = (float)labels[i];
    if (k == BN) return;

    // ================= exact fallback from first non-insert =================
    if (tid == 0) {
        unsigned arg = (unsigned)(g_rowmin[k] & 0xffffffffu);
        out[k] = (float)labels[arg];
        float a = INFV, b = 0.0f;
        for (int i = 1; i <= k; ++i) { a = fminf(a, s_minA[i]); b = fmaxf(b, s_maxA[i]); }
        sh_minD = a; sh_maxD = b; sh_R = (a + b) / 3.0f; sh_n = k;
    }
    for (int i = tid; i < BN; i += 1024) {
        s_norm[i] = g_norm[i];
        s_lab[i]  = (unsigned char)labels[i];
    }
    for (int j = tid; j < k; j += 1024) s_ridx[j] = (unsigned short)j;
    __syncthreads();

    for (int i = k + 1; i < BN; ++i) {
        const int n = sh_n;
        const float ni = s_norm[i];
        const float* __restrict__ Grow = g_G + (size_t)i * BN;

        float lmin = INFV;
        int   larg = 0x7fffffff;
        float lmax = -INFV;
        for (int j = tid; j < n; j += 1024) {
            int r = s_ridx[j];
            float d2 = fmaf(-2.0f, __ldg(Grow + r), ni + s_norm[r]);
            if (d2 < lmin) { lmin = d2; larg = j; }
            lmax = fmaxf(lmax, d2);
        }
#pragma unroll
        for (int off = 16; off > 0; off >>= 1) {
            float v = __shfl_down_sync(0xffffffffu, lmin, off);
            int   a = __shfl_down_sync(0xffffffffu, larg, off);
            float m = __shfl_down_sync(0xffffffffu, lmax, off);
            if (v < lmin || (v == lmin && a < larg)) { lmin = v; larg = a; }
            lmax = fmaxf(lmax, m);
        }
        if (lane == 0) { r_min[wid] = lmin; r_arg[wid] = larg; r_max[wid] = lmax; }
        __syncthreads();

        if (tid == 0) {
            float bm = r_min[0]; int ba = r_arg[0]; float bx = r_max[0];
#pragma unroll
            for (int w = 1; w < 32; ++w) {
                float v = r_min[w]; int a = r_arg[w];
                if (v < bm || (v == bm && a < ba)) { bm = v; ba = a; }
                bx = fmaxf(bx, r_max[w]);
            }
            const float min_act = sqrtf(fmaxf(bm, 0.0f));
            const bool insert = (min_act > sh_R);
            float pred;
            if (insert) {
                s_ridx[n] = (unsigned short)i;
                sh_n = n + 1;
                pred = (float)s_lab[i];
            } else {
                pred = (float)s_lab[s_ridx[ba]];
            }
            const float max_act = sqrtf(fmaxf(bx, 0.0f));
            sh_minD = fminf(sh_minD, min_act);
            sh_maxD = fmaxf(sh_maxD, max_act);
            sh_R = (sh_minD + sh_maxD) / 3.0f;
            out[i] = pred;
        }
        __syncthreads();
    }
}

// ---------------------------------------------------------------------------
extern "C" void kernel_launch(void* const* d_in, const int* in_sizes, int n_in,
                              void* d_out, int out_size) {
    const float* x      = (const float*)d_in[0];
    const int*   labels = (const int*)d_in[1];
    float*       out    = (float*)d_out;

    static bool attr_set = false;
    if (!attr_set) {
        cudaFuncSetAttribute(scan_kernel, cudaFuncAttributeMaxDynamicSharedMemorySize, 61440);
        attr_set = true;
    }

    convert_kernel<<<(BN * DK / 4) / 256, 256>>>(x);
    norm_kernel<<<BN / 8, 256>>>(x);
    init_stats<<<BN / 256, 256>>>();
    const int nb = BN / TM;
    gram_mma<<<nb * (nb + 1) / 2, 256>>>();
    scan_kernel<<<1, 1024, 61440>>>(labels, out);
}